// round 8
// baseline (speedup 1.0000x reference)
#include <cuda_runtime.h>

// Bloch-vector formulation (exact rewrite of the circuit, verified R6):
//   n_enc = (sin(pi x1)cos(pi x2), sin(pi x1)sin(pi x2), cos(pi x1))
//   z_q = r_q . n_enc ; h_q = s_q . n_enc
//   Z0 = a0 z_a + h_a z_b          Z1 = a1 z_b + h_b z_a z_c
//   Z2 = a2 z_c + h_c z_b z_d      Z3 = a3 z_d + h_d z_c
//
// Input streamed via cp.async.bulk (TMA bulk copy) into shared memory to
// escape the per-SM LDG outstanding-line cap (~2.4 TB/s measured) and reach
// the HBM stream rate. One 12 KB tile (256 lines) per block, 1024 blocks.

#define TILE_LINES 256
#define TILE_BYTES (TILE_LINES * 48)   // 12288

__global__ __launch_bounds__(256)
void qcnn_kernel(const float* __restrict__ x, const float* __restrict__ w,
                 float* __restrict__ out) {
    __shared__ alignas(128) float4 tile[TILE_LINES * 3];   // 12288 B
    __shared__ float4 sc[8];           // sc[q]=(r3,a_q), sc[4+q]=(s,0)
    __shared__ alignas(8) unsigned long long mbar;

    int tid = threadIdx.x;
    unsigned mb = (unsigned)__cvta_generic_to_shared(&mbar);

    if (tid == 0) {
        asm volatile("mbarrier.init.shared.b64 [%0], %1;" :: "r"(mb), "r"(1));
    }

    if (tid < 4) {
        int q = tid;
        // ---- layer-1 gate U1 = RZ(g)RY(b)RX(a): need u00, u10 only ----
        float a1 = __ldg(w + q * 3 + 0), b1 = __ldg(w + q * 3 + 1),
              g1 = __ldg(w + q * 3 + 2);
        float sa, ca, sb, cb, sg, cg;
        __sincosf(0.5f * a1, &sa, &ca);
        __sincosf(0.5f * b1, &sb, &cb);
        __sincosf(0.5f * g1, &sg, &cg);
        float m00r = cb * ca, m00i = sb * sa;
        float m10r = sb * ca, m10i = -cb * sa;
        float u00r = cg * m00r + sg * m00i, u00i = cg * m00i - sg * m00r;
        float u10r = cg * m10r - sg * m10i, u10i = cg * m10i + sg * m10r;
        // SU(2) -> quaternion (t,x,y,z)
        float qt = u00r, qz = -u00i, qy = u10r, qx = -u10i;
        float r1x = 1.f - 2.f * (qy * qy + qz * qz);
        float r1y = 2.f * (qx * qy - qt * qz);
        float r1z = 2.f * (qx * qz + qt * qy);
        float r2x = 2.f * (qx * qy + qt * qz);
        float r2y = 1.f - 2.f * (qx * qx + qz * qz);
        float r2z = 2.f * (qy * qz - qt * qx);
        float r3x = 2.f * (qx * qz - qt * qy);
        float r3y = 2.f * (qy * qz + qt * qx);
        float r3z = 1.f - 2.f * (qx * qx + qy * qy);

        // ---- layer-2 gate U2 -> observable M = U2^dag Z U2 ----
        float a2 = __ldg(w + 12 + q * 3 + 0), b2 = __ldg(w + 12 + q * 3 + 1),
              g2 = __ldg(w + 12 + q * 3 + 2);
        __sincosf(0.5f * a2, &sa, &ca);
        __sincosf(0.5f * b2, &sb, &cb);
        __sincosf(0.5f * g2, &sg, &cg);
        float n00r = cb * ca, n00i = sb * sa;
        float n01r = -sb * ca, n01i = -cb * sa;
        float n10r = sb * ca, n10i = -cb * sa;
        float n11r = cb * ca, n11i = -sb * sa;
        float v00r = cg * n00r + sg * n00i, v00i = cg * n00i - sg * n00r;
        float v01r = cg * n01r + sg * n01i, v01i = cg * n01i - sg * n01r;
        float v10r = cg * n10r - sg * n10i, v10i = cg * n10i + sg * n10r;
        float v11r = cg * n11r - sg * n11i, v11i = cg * n11i + sg * n11r;
        float ma = v00r * v00r + v00i * v00i - v10r * v10r - v10i * v10i;
        float mb2 = v00r * v01r + v00i * v01i - (v10r * v11r + v10i * v11i);
        float mc = v00r * v01i - v00i * v01r - (v10r * v11i - v10i * v11r);

        sc[q]     = make_float4(r3x, r3y, r3z, ma);
        sc[4 + q] = make_float4(mb2 * r1x - mc * r2x,
                                mb2 * r1y - mc * r2y,
                                mb2 * r1z - mc * r2z, 0.f);
    }
    __syncthreads();   // mbarrier init + constants visible

    if (tid == 0) {
        unsigned dst = (unsigned)__cvta_generic_to_shared(tile);
        const char* src = (const char*)x + (size_t)blockIdx.x * TILE_BYTES;
        asm volatile("mbarrier.arrive.expect_tx.shared.b64 _, [%0], %1;"
                     :: "r"(mb), "r"(TILE_BYTES) : "memory");
        asm volatile(
            "cp.async.bulk.shared::cta.global.mbarrier::complete_tx::bytes "
            "[%0], [%1], %2, [%3];"
            :: "r"(dst), "l"(src), "r"(TILE_BYTES), "r"(mb) : "memory");
    }

    // wait for the tile (phase parity 0)
    {
        unsigned done;
        asm volatile(
            "{\n\t.reg .pred p;\n\t"
            "mbarrier.try_wait.parity.acquire.cta.shared::cta.b64 p, [%1], 0;\n\t"
            "selp.b32 %0, 1, 0, p;\n\t}"
            : "=r"(done) : "r"(mb) : "memory");
        if (!done) {
            asm volatile(
                "{\n\t.reg .pred P1;\n\t"
                "W_%=:\n\t"
                "mbarrier.try_wait.parity.acquire.cta.shared::cta.b64 P1, [%0], 0, 0x989680;\n\t"
                "@P1 bra.uni D_%=;\n\t"
                "bra.uni W_%=;\n\t"
                "D_%=:\n\t}"
                :: "r"(mb) : "memory");
        }
    }

    // this thread's line: 48 B = 3 float4 (stride-3 float4 LDS: conflict-free)
    float4 F0 = tile[tid * 3 + 0];
    float4 F1 = tile[tid * 3 + 1];
    float4 F2 = tile[tid * 3 + 2];

    const float PI = 3.14159265358979323846f;
    float s1, c1, s2, c2;
    // qubit 0
    __sincosf(PI * F0.y, &s1, &c1);
    __sincosf(PI * F0.z, &s2, &c2);
    float xe = s1 * c2, ye = s1 * s2, ze = c1;
    float4 r = sc[0], s = sc[4];
    float za = fmaf(r.z, ze, fmaf(r.y, ye, r.x * xe));
    float ha = fmaf(s.z, ze, fmaf(s.y, ye, s.x * xe));
    float aza = r.w * za;
    // qubit 1
    __sincosf(PI * F1.x, &s1, &c1);
    __sincosf(PI * F1.y, &s2, &c2);
    xe = s1 * c2; ye = s1 * s2; ze = c1;
    r = sc[1]; s = sc[5];
    float zb = fmaf(r.z, ze, fmaf(r.y, ye, r.x * xe));
    float hb = fmaf(s.z, ze, fmaf(s.y, ye, s.x * xe));
    float azb = r.w * zb;
    // qubit 2
    __sincosf(PI * F1.w, &s1, &c1);
    __sincosf(PI * F2.x, &s2, &c2);
    xe = s1 * c2; ye = s1 * s2; ze = c1;
    r = sc[2]; s = sc[6];
    float zc = fmaf(r.z, ze, fmaf(r.y, ye, r.x * xe));
    float hc = fmaf(s.z, ze, fmaf(s.y, ye, s.x * xe));
    float azc = r.w * zc;
    // qubit 3
    __sincosf(PI * F2.z, &s1, &c1);
    __sincosf(PI * F2.w, &s2, &c2);
    xe = s1 * c2; ye = s1 * s2; ze = c1;
    r = sc[3]; s = sc[7];
    float zd = fmaf(r.z, ze, fmaf(r.y, ye, r.x * xe));
    float hd = fmaf(s.z, ze, fmaf(s.y, ye, s.x * xe));
    float azd = r.w * zd;

    float4 Z = make_float4(fmaf(ha, zb, aza),
                           fmaf(hb, za * zc, azb),
                           fmaf(hc, zb * zd, azc),
                           fmaf(hd, zc, azd));

    ((float4*)out)[blockIdx.x * TILE_LINES + tid] = Z;
}

extern "C" void kernel_launch(void* const* d_in, const int* in_sizes, int n_in,
                              void* d_out, int out_size) {
    const float* x = (const float*)d_in[0];   // [128, 2048, 4, 3] f32
    const float* w = (const float*)d_in[1];   // [2, 4, 3] f32
    float* out = (float*)d_out;               // [128, 2048, 4] f32

    int nlines = in_sizes[0] / 12;            // 262144
    int grid = nlines / TILE_LINES;           // 1024 tiles, one per block
    qcnn_kernel<<<grid, TILE_LINES>>>(x, w, out);
}